// round 10
// baseline (speedup 1.0000x reference)
#include <cuda_runtime.h>
#include <cuda_fp16.h>
#include <math_constants.h>

#define NE 100000
#define NR 1000
#define EC 1000000
#define HID 128
#define OUTD 256
#define N2 (2 * NE)
#define SCAN_B 1024
#define SCAN_NB ((N2 + SCAN_B - 1) / SCAN_B)   // 196

// ---- scratch (device globals: allocation-free) ----
__device__ float  g_eh[NE];
__device__ float  g_et[NE];
__device__ float  g_er[NR];
__device__ float  g_lh[EC];
__device__ float  g_lt[EC];
__device__ float  g_hs[NR * 256];      // MLP hidden layer
__device__ float  g_msg[NR * HID];     // msg = x_r + mlp(x_r)
__device__ __half g_tWh[NR * OUTD];
__device__ __half g_tWt[NR * OUTD];
__device__ int    g_hist[N2];
__device__ int    g_off[N2];
__device__ int    g_cur[N2];
__device__ int    g_idx[2 * EC];
__device__ int    g_part[SCAN_NB];
__device__ int    g_partoff[SCAN_NB];

// ---- zero histograms ----
__global__ void k_zero_hist() {
    int i = blockIdx.x * blockDim.x + threadIdx.x;
    if (i < N2) g_hist[i] = 0;
}

// ---- per-entity attention scores: warp per node ----
__global__ void k_node_scores(const float* __restrict__ xe,
                              const float* __restrict__ wah,
                              const float* __restrict__ wat) {
    int warp = (blockIdx.x * blockDim.x + threadIdx.x) >> 5;
    int lane = threadIdx.x & 31;
    if (warp >= NE) return;
    const float4* row = (const float4*)(xe + (size_t)warp * HID);
    float4 v = row[lane];
    float4 a = ((const float4*)wah)[lane];
    float4 b = ((const float4*)wat)[lane];
    float sh = v.x * a.x + v.y * a.y + v.z * a.z + v.w * a.w;
    float st = v.x * b.x + v.y * b.y + v.z * b.z + v.w * b.w;
    #pragma unroll
    for (int o = 16; o; o >>= 1) {
        sh += __shfl_xor_sync(0xFFFFFFFFu, sh, o);
        st += __shfl_xor_sync(0xFFFFFFFFu, st, o);
    }
    if (lane == 0) { g_eh[warp] = sh; g_et[warp] = st; }
}

// ---- per-relation attention scores: warp per relation ----
__global__ void k_rel_scores(const float* __restrict__ xr,
                             const float* __restrict__ war) {
    int warp = (blockIdx.x * blockDim.x + threadIdx.x) >> 5;
    int lane = threadIdx.x & 31;
    if (warp >= NR) return;
    const float4* row = (const float4*)(xr + (size_t)warp * HID);
    float4 v = row[lane];
    float4 a = ((const float4*)war)[lane];
    float s = v.x * a.x + v.y * a.y + v.z * a.z + v.w * a.w;
    #pragma unroll
    for (int o = 16; o; o >>= 1) s += __shfl_xor_sync(0xFFFFFFFFu, s, o);
    if (lane == 0) g_er[warp] = s;
}

// ---- MLP layer 1: g_hs = x_r @ W1 + b1   [1000,128]@[128,256]
// grid 250, block 256 = 4 rels x 64 col-groups(4 cols)
__global__ __launch_bounds__(256) void k_l1(const float* __restrict__ xr,
                                            const float* __restrict__ W1,
                                            const float* __restrict__ b1) {
    __shared__ float xs[4][HID];
    int r0 = blockIdx.x * 4;
    int tid = threadIdx.x;
    int rl = tid >> 6;       // 0..3
    int cg = tid & 63;       // cols 4cg..4cg+3
    for (int i = tid; i < 4 * HID; i += 256)
        xs[i >> 7][i & 127] = xr[(size_t)(r0 + (i >> 7)) * HID + (i & 127)];
    __syncthreads();
    float4 acc = make_float4(0.f, 0.f, 0.f, 0.f);
    #pragma unroll 4
    for (int k = 0; k < HID; k++) {
        float4 w = *(const float4*)&W1[k * 256 + 4 * cg];
        float x = xs[rl][k];
        acc.x += x * w.x; acc.y += x * w.y; acc.z += x * w.z; acc.w += x * w.w;
    }
    float4 bb = *(const float4*)&b1[4 * cg];
    acc.x += bb.x; acc.y += bb.y; acc.z += bb.z; acc.w += bb.w;
    *(float4*)&g_hs[(size_t)(r0 + rl) * 256 + 4 * cg] = acc;
}

// ---- MLP layer 2 + residual: g_msg = x_r + g_hs @ W2 + b2   [1000,256]@[256,128]
// grid 250, block 128 = 4 rels x 32 col-groups
__global__ __launch_bounds__(128) void k_l2(const float* __restrict__ xr,
                                            const float* __restrict__ W2,
                                            const float* __restrict__ b2) {
    __shared__ float hs[4][256];
    int r0 = blockIdx.x * 4;
    int tid = threadIdx.x;
    int rl = tid >> 5;       // 0..3
    int cg = tid & 31;       // cols 4cg..4cg+3
    for (int i = tid; i < 4 * 256; i += 128)
        hs[i >> 8][i & 255] = g_hs[(size_t)(r0 + (i >> 8)) * 256 + (i & 255)];
    __syncthreads();
    float4 acc = make_float4(0.f, 0.f, 0.f, 0.f);
    #pragma unroll 4
    for (int j = 0; j < 256; j++) {
        float4 w = *(const float4*)&W2[j * 128 + 4 * cg];
        float x = hs[rl][j];
        acc.x += x * w.x; acc.y += x * w.y; acc.z += x * w.z; acc.w += x * w.w;
    }
    float4 xv = *(const float4*)&xr[(size_t)(r0 + rl) * HID + 4 * cg];
    float4 bb = *(const float4*)&b2[4 * cg];
    acc.x += xv.x + bb.x; acc.y += xv.y + bb.y;
    acc.z += xv.z + bb.z; acc.w += xv.w + bb.w;
    *(float4*)&g_msg[(size_t)(r0 + rl) * HID + 4 * cg] = acc;
}

// ---- MLP layer 3: fold output projection; both table halves
// grid 250, block 512 = 2 halves x 4 rels x 64 col-groups
__global__ __launch_bounds__(512) void k_l3(const float* __restrict__ Wr) {
    __shared__ float ms[4][HID];
    int r0 = blockIdx.x * 4;
    int tid = threadIdx.x;
    int half = tid >> 8;           // 0: h-table, 1: t-table
    int rl   = (tid >> 6) & 3;
    int cg   = tid & 63;
    for (int i = tid; i < 4 * HID; i += 512)
        ms[i >> 7][i & 127] = g_msg[(size_t)(r0 + (i >> 7)) * HID + (i & 127)];
    __syncthreads();
    float4 acc = make_float4(0.f, 0.f, 0.f, 0.f);
    #pragma unroll 4
    for (int k = 0; k < HID; k++) {
        float4 w = *(const float4*)&Wr[(size_t)(half * HID + k) * 256 + 4 * cg];
        float x = ms[rl][k];
        acc.x += x * w.x; acc.y += x * w.y; acc.z += x * w.z; acc.w += x * w.w;
    }
    __half2 h0 = __floats2half2_rn(acc.x, acc.y);
    __half2 h1 = __floats2half2_rn(acc.z, acc.w);
    uint2 pk = make_uint2(*(unsigned*)&h0, *(unsigned*)&h1);
    __half* dst = half ? g_tWt : g_tWh;
    *(uint2*)&dst[(size_t)(r0 + rl) * OUTD + 4 * cg] = pk;
}

// ---- edge pass: logits + degree histogram ----
__global__ void k_logits(const int* __restrict__ ei, const int* __restrict__ rel) {
    int e = blockIdx.x * blockDim.x + threadIdx.x;
    if (e >= EC) return;
    int h = ei[e], t = ei[EC + e], r = rel[e];
    float er = g_er[r];
    float lh = g_eh[h] + er;
    lh = lh > 0.0f ? lh : 0.01f * lh;
    float lt = g_et[t] + er;
    lt = lt > 0.0f ? lt : 0.01f * lt;
    g_lh[e] = lh;
    g_lt[e] = lt;
    atomicAdd(&g_hist[h], 1);
    atomicAdd(&g_hist[NE + t], 1);
}

// ---- scan stage 1 ----
__global__ void k_scan1() {
    __shared__ int sh[SCAN_B];
    int t = threadIdx.x;
    int i = blockIdx.x * SCAN_B + t;
    int v = (i < N2) ? g_hist[i] : 0;
    sh[t] = v;
    __syncthreads();
    #pragma unroll
    for (int d = 1; d < SCAN_B; d <<= 1) {
        int x = (t >= d) ? sh[t - d] : 0;
        __syncthreads();
        sh[t] += x;
        __syncthreads();
    }
    if (i < N2) g_off[i] = sh[t] - v;
    if (t == SCAN_B - 1) g_part[blockIdx.x] = sh[t];
}

// ---- scan stage 2 ----
__global__ void k_scan2() {
    if (threadIdx.x == 0) {
        int run = 0;
        for (int b = 0; b < SCAN_NB; b++) {
            g_partoff[b] = run;
            run += g_part[b];
        }
    }
}

// ---- scan stage 3 ----
__global__ void k_scan3() {
    int i = blockIdx.x * blockDim.x + threadIdx.x;
    if (i < N2) {
        int o = g_off[i] + g_partoff[i / SCAN_B];
        g_off[i] = o;
        g_cur[i] = o;
    }
}

// ---- CSR fill ----
__global__ void k_fill(const int* __restrict__ ei) {
    int e = blockIdx.x * blockDim.x + threadIdx.x;
    if (e >= EC) return;
    int h = ei[e], t = ei[EC + e];
    int p = atomicAdd(&g_cur[h], 1);
    g_idx[p] = e;
    int q = atomicAdd(&g_cur[NE + t], 1);
    g_idx[q] = e;
}

// ---- fma 8 halfs into fp32 accumulators ----
__device__ __forceinline__ void fma8(float* acc, uint4 p, float a) {
    __half2* h = reinterpret_cast<__half2*>(&p);
    #pragma unroll
    for (int q = 0; q < 4; q++) {
        float2 f = __half22float2(h[q]);
        acc[2 * q]     += a * f.x;
        acc[2 * q + 1] += a * f.y;
    }
}

// ---- segment softmax + weighted half-table accumulation ----
__device__ __forceinline__ void seg_accum(int base, int deg, int lane,
                                          const float* __restrict__ lg,
                                          const int* __restrict__ rel,
                                          const __half* __restrict__ table,
                                          float* acc) {
    if (deg <= 0) return;
    if (deg <= 32) {
        float l = -CUDART_INF_F;
        int r = 0;
        if (lane < deg) {
            int e = g_idx[base + lane];
            l = lg[e];
            r = rel[e];
        }
        float m = l;
        #pragma unroll
        for (int o = 16; o; o >>= 1) m = fmaxf(m, __shfl_xor_sync(0xFFFFFFFFu, m, o));
        float z = (lane < deg) ? __expf(l - m) : 0.0f;
        float s = z;
        #pragma unroll
        for (int o = 16; o; o >>= 1) s += __shfl_xor_sync(0xFFFFFFFFu, s, o);
        float a_own = z / (s + 1e-16f);
        for (int j = 0; j < deg; j++) {
            float a = __shfl_sync(0xFFFFFFFFu, a_own, j);
            int rj  = __shfl_sync(0xFFFFFFFFu, r, j);
            uint4 p = ((const uint4*)(table + (size_t)rj * OUTD))[lane];
            fma8(acc, p, a);
        }
    } else {
        float m = -CUDART_INF_F;
        for (int j = lane; j < deg; j += 32) m = fmaxf(m, lg[g_idx[base + j]]);
        #pragma unroll
        for (int o = 16; o; o >>= 1) m = fmaxf(m, __shfl_xor_sync(0xFFFFFFFFu, m, o));
        float s = 0.0f;
        for (int j = lane; j < deg; j += 32) s += __expf(lg[g_idx[base + j]] - m);
        #pragma unroll
        for (int o = 16; o; o >>= 1) s += __shfl_xor_sync(0xFFFFFFFFu, s, o);
        float inv = 1.0f / (s + 1e-16f);
        for (int c0 = 0; c0 < deg; c0 += 32) {
            int j = c0 + lane;
            float a_own = 0.0f;
            int r = 0;
            if (j < deg) {
                int e = g_idx[base + j];
                a_own = __expf(lg[e] - m) * inv;
                r = rel[e];
            }
            int cnt = min(32, deg - c0);
            for (int jj = 0; jj < cnt; jj++) {
                float a = __shfl_sync(0xFFFFFFFFu, a_own, jj);
                int rj  = __shfl_sync(0xFFFFFFFFu, r, jj);
                uint4 p = ((const uint4*)(table + (size_t)rj * OUTD))[lane];
                fma8(acc, p, a);
            }
        }
    }
}

// ---- gather: one warp per node, both directions, single row store ----
__global__ void k_gather(const int* __restrict__ rel,
                         const float* __restrict__ br,
                         float* __restrict__ out) {
    int n = (blockIdx.x * blockDim.x + threadIdx.x) >> 5;
    int lane = threadIdx.x & 31;
    if (n >= NE) return;

    float acc[8];
    #pragma unroll
    for (int q = 0; q < 8; q++) acc[q] = 0.0f;

    seg_accum(g_off[n],      g_hist[n],      lane, g_lh, rel, g_tWh, acc);
    seg_accum(g_off[NE + n], g_hist[NE + n], lane, g_lt, rel, g_tWt, acc);

    float4 b0 = ((const float4*)(br + lane * 8))[0];
    float4 b1 = ((const float4*)(br + lane * 8))[1];
    float4* o = (float4*)(out + (size_t)n * OUTD + lane * 8);
    o[0] = make_float4(acc[0] + b0.x, acc[1] + b0.y, acc[2] + b0.z, acc[3] + b0.w);
    o[1] = make_float4(acc[4] + b1.x, acc[5] + b1.y, acc[6] + b1.z, acc[7] + b1.w);
}

extern "C" void kernel_launch(void* const* d_in, const int* in_sizes, int n_in,
                              void* d_out, int out_size) {
    const float* x_e  = (const float*)d_in[0];
    const float* x_r  = (const float*)d_in[1];
    const int*   ei   = (const int*)d_in[2];
    const int*   rel  = (const int*)d_in[3];
    const float* w_ah = (const float*)d_in[5];
    const float* w_at = (const float*)d_in[6];
    const float* w_ar = (const float*)d_in[7];
    const float* W1   = (const float*)d_in[8];
    const float* b1   = (const float*)d_in[9];
    const float* W2   = (const float*)d_in[10];
    const float* b2   = (const float*)d_in[11];
    const float* Wr   = (const float*)d_in[12];
    const float* br   = (const float*)d_in[13];
    float* out = (float*)d_out;

    k_zero_hist<<<(N2 + 255) / 256, 256>>>();
    k_node_scores<<<(NE + 7) / 8, 256>>>(x_e, w_ah, w_at);
    k_rel_scores<<<(NR + 7) / 8, 256>>>(x_r, w_ar);
    k_l1<<<NR / 4, 256>>>(x_r, W1, b1);
    k_l2<<<NR / 4, 128>>>(x_r, W2, b2);
    k_l3<<<NR / 4, 512>>>(Wr);
    k_logits<<<(EC + 255) / 256, 256>>>(ei, rel);
    k_scan1<<<SCAN_NB, SCAN_B>>>();
    k_scan2<<<1, 32>>>();
    k_scan3<<<(N2 + 255) / 256, 256>>>();
    k_fill<<<(EC + 255) / 256, 256>>>(ei);
    k_gather<<<(NE + 7) / 8, 256>>>(rel, br, out);
}

// round 11
// speedup vs baseline: 1.2111x; 1.2111x over previous
#include <cuda_runtime.h>
#include <cuda_fp16.h>
#include <math_constants.h>

#define NE 100000
#define NR 1000
#define EC 1000000
#define HID 128
#define OUTD 256
#define N2 (2 * NE)
#define SCAN_B 1024
#define SCAN_NB ((N2 + SCAN_B - 1) / SCAN_B)   // 196
#define RT 8                                    // relations per MLP block

// block-range dispatch for the fused front kernel
#define MLP_NB 125
#define Z_NB   ((N2 + 1023) / 1024)            // 196
#define NS_NB  ((NE + 31) / 32)                // 3125  (warp per node, 32 warps/block)
#define RS_NB  ((NR + 31) / 32)                // 32
#define FRONT_NB (MLP_NB + Z_NB + NS_NB + RS_NB)

// ---- scratch (device globals: allocation-free) ----
__device__ float  g_eh[NE];
__device__ float  g_et[NE];
__device__ float  g_er[NR];
__device__ float  g_lh[EC];
__device__ float  g_lt[EC];
__device__ __half g_tWh[NR * OUTD];
__device__ __half g_tWt[NR * OUTD];
__device__ int    g_hist[N2];
__device__ int    g_off[N2];
__device__ int    g_cur[N2];
__device__ int    g_idx[2 * EC];
__device__ int    g_part[SCAN_NB];
__device__ int    g_partoff[SCAN_NB];

// ---- fused front kernel: MLP blocks + zero_hist + node_scores + rel_scores ----
__global__ __launch_bounds__(1024) void k_front(
        const float* __restrict__ xr,
        const float* __restrict__ W1, const float* __restrict__ b1,
        const float* __restrict__ W2, const float* __restrict__ b2,
        const float* __restrict__ Wr,
        const float* __restrict__ xe,
        const float* __restrict__ wah, const float* __restrict__ wat,
        const float* __restrict__ war) {
    __shared__ float xs[RT][HID];        // x_r rows; becomes msg after layer 2
    __shared__ float hs[RT][2 * HID];    // hidden layer
    __shared__ float red[8192];          // 32 KB reduction buffer
    int bid = blockIdx.x;
    int tid = threadIdx.x;               // 1024 threads

    if (bid < MLP_NB) {
        // ================= fused relation MLP + W_r fold =================
        int r0 = bid * RT;
        int rh = tid >> 8;               // relation subset: rels rh*2, rh*2+1

        for (int i = tid; i < RT * HID; i += 1024) {
            int rr = i >> 7, c = i & 127;
            xs[rr][c] = xr[(size_t)(r0 + rr) * HID + c];
        }
        __syncthreads();

        // layer 1: hs[i][c] = b1[c] + sum_k xs[i][k] * W1[k*256+c]
        {
            int kk = (tid >> 6) & 3;     // k-group 0..3
            int u  = tid & 63;           // cols 4u..4u+3
            float4 acc[2];
            #pragma unroll
            for (int i = 0; i < 2; i++) acc[i] = make_float4(0.f, 0.f, 0.f, 0.f);
            #pragma unroll 4
            for (int m = 0; m < 32; m++) {
                int k = kk + 4 * m;
                float4 w = *(const float4*)&W1[k * 256 + 4 * u];
                #pragma unroll
                for (int i = 0; i < 2; i++) {
                    float x = xs[rh * 2 + i][k];
                    acc[i].x += x * w.x; acc[i].y += x * w.y;
                    acc[i].z += x * w.z; acc[i].w += x * w.w;
                }
            }
            #pragma unroll
            for (int i = 0; i < 2; i++)
                *(float4*)&red[(kk * 8 + rh * 2 + i) * 256 + 4 * u] = acc[i];
            __syncthreads();
            #pragma unroll
            for (int p = 0; p < 2; p++) {
                int idx = p * 1024 + tid;      // 2048 outputs
                int i = idx >> 8, c = idx & 255;
                hs[i][c] = b1[c] + red[(0 + i) * 256 + c] + red[(8 + i) * 256 + c]
                         + red[(16 + i) * 256 + c] + red[(24 + i) * 256 + c];
            }
            __syncthreads();
        }

        // layer 2 + residual
        {
            int jj = (tid >> 5) & 7;     // j-group 0..7
            int u  = tid & 31;           // cols 4u..4u+3
            float4 acc[2];
            #pragma unroll
            for (int i = 0; i < 2; i++) acc[i] = make_float4(0.f, 0.f, 0.f, 0.f);
            #pragma unroll 4
            for (int m = 0; m < 32; m++) {
                int j = jj + 8 * m;
                float4 w = *(const float4*)&W2[j * 128 + 4 * u];
                #pragma unroll
                for (int i = 0; i < 2; i++) {
                    float x = hs[rh * 2 + i][j];
                    acc[i].x += x * w.x; acc[i].y += x * w.y;
                    acc[i].z += x * w.z; acc[i].w += x * w.w;
                }
            }
            #pragma unroll
            for (int i = 0; i < 2; i++)
                *(float4*)&red[(jj * 8 + rh * 2 + i) * 128 + 4 * u] = acc[i];
            __syncthreads();
            {
                int idx = tid;                 // 1024 outputs
                int i = idx >> 7, c = idx & 127;
                float v = b2[c];
                #pragma unroll
                for (int g = 0; g < 8; g++) v += red[(g * 8 + i) * 128 + c];
                xs[i][c] += v;                 // msg = x_r + mlp(x_r)
            }
            __syncthreads();
        }

        // layer 3: folded tables
        {
            int half = (tid >> 7) & 1;   // 0: h-table, 1: t-table
            int kk   = (tid >> 6) & 1;   // k-group 0,1
            int u    = tid & 63;         // cols 4u..4u+3
            float4 acc[2];
            #pragma unroll
            for (int i = 0; i < 2; i++) acc[i] = make_float4(0.f, 0.f, 0.f, 0.f);
            #pragma unroll 4
            for (int m = 0; m < 64; m++) {
                int k = kk + 2 * m;
                float4 w = *(const float4*)&Wr[(half * 128 + k) * 256 + 4 * u];
                #pragma unroll
                for (int i = 0; i < 2; i++) {
                    float x = xs[rh * 2 + i][k];
                    acc[i].x += x * w.x; acc[i].y += x * w.y;
                    acc[i].z += x * w.z; acc[i].w += x * w.w;
                }
            }
            #pragma unroll
            for (int i = 0; i < 2; i++)
                *(float4*)&red[((kk * 2 + half) * 8 + rh * 2 + i) * 256 + 4 * u] = acc[i];
            __syncthreads();
            #pragma unroll
            for (int p = 0; p < 4; p++) {
                int idx = p * 1024 + tid;      // 4096 outputs
                int c = idx & 255;
                int q = idx >> 8;              // 0..15
                int i = q & 7, hf = q >> 3;
                float v = red[((0 + hf) * 8 + i) * 256 + c]
                        + red[((2 + hf) * 8 + i) * 256 + c];
                if (hf == 0) g_tWh[(size_t)(r0 + i) * OUTD + c] = __float2half(v);
                else         g_tWt[(size_t)(r0 + i) * OUTD + c] = __float2half(v);
            }
        }
    } else if (bid < MLP_NB + Z_NB) {
        // ================= zero histograms =================
        int i = (bid - MLP_NB) * 1024 + tid;
        if (i < N2) g_hist[i] = 0;
    } else if (bid < MLP_NB + Z_NB + NS_NB) {
        // ================= per-entity attention scores (warp per node) =====
        int warp = (bid - MLP_NB - Z_NB) * 32 + (tid >> 5);
        int lane = tid & 31;
        if (warp < NE) {
            const float4* row = (const float4*)(xe + (size_t)warp * HID);
            float4 v = row[lane];
            float4 a = ((const float4*)wah)[lane];
            float4 b = ((const float4*)wat)[lane];
            float sh = v.x * a.x + v.y * a.y + v.z * a.z + v.w * a.w;
            float st = v.x * b.x + v.y * b.y + v.z * b.z + v.w * b.w;
            #pragma unroll
            for (int o = 16; o; o >>= 1) {
                sh += __shfl_xor_sync(0xFFFFFFFFu, sh, o);
                st += __shfl_xor_sync(0xFFFFFFFFu, st, o);
            }
            if (lane == 0) { g_eh[warp] = sh; g_et[warp] = st; }
        }
    } else {
        // ================= per-relation attention scores (warp per rel) ====
        int warp = (bid - MLP_NB - Z_NB - NS_NB) * 32 + (tid >> 5);
        int lane = tid & 31;
        if (warp < NR) {
            const float4* row = (const float4*)(xr + (size_t)warp * HID);
            float4 v = row[lane];
            float4 a = ((const float4*)war)[lane];
            float s = v.x * a.x + v.y * a.y + v.z * a.z + v.w * a.w;
            #pragma unroll
            for (int o = 16; o; o >>= 1) s += __shfl_xor_sync(0xFFFFFFFFu, s, o);
            if (lane == 0) g_er[warp] = s;
        }
    }
}

// ---- edge pass: logits + degree histogram ----
__global__ void k_logits(const int* __restrict__ ei, const int* __restrict__ rel) {
    int e = blockIdx.x * blockDim.x + threadIdx.x;
    if (e >= EC) return;
    int h = ei[e], t = ei[EC + e], r = rel[e];
    float er = g_er[r];
    float lh = g_eh[h] + er;
    lh = lh > 0.0f ? lh : 0.01f * lh;
    float lt = g_et[t] + er;
    lt = lt > 0.0f ? lt : 0.01f * lt;
    g_lh[e] = lh;
    g_lt[e] = lt;
    atomicAdd(&g_hist[h], 1);
    atomicAdd(&g_hist[NE + t], 1);
}

// ---- scan stage 1 ----
__global__ void k_scan1() {
    __shared__ int sh[SCAN_B];
    int t = threadIdx.x;
    int i = blockIdx.x * SCAN_B + t;
    int v = (i < N2) ? g_hist[i] : 0;
    sh[t] = v;
    __syncthreads();
    #pragma unroll
    for (int d = 1; d < SCAN_B; d <<= 1) {
        int x = (t >= d) ? sh[t - d] : 0;
        __syncthreads();
        sh[t] += x;
        __syncthreads();
    }
    if (i < N2) g_off[i] = sh[t] - v;
    if (t == SCAN_B - 1) g_part[blockIdx.x] = sh[t];
}

// ---- scan stage 2 ----
__global__ void k_scan2() {
    if (threadIdx.x == 0) {
        int run = 0;
        for (int b = 0; b < SCAN_NB; b++) {
            g_partoff[b] = run;
            run += g_part[b];
        }
    }
}

// ---- scan stage 3 ----
__global__ void k_scan3() {
    int i = blockIdx.x * blockDim.x + threadIdx.x;
    if (i < N2) {
        int o = g_off[i] + g_partoff[i / SCAN_B];
        g_off[i] = o;
        g_cur[i] = o;
    }
}

// ---- CSR fill ----
__global__ void k_fill(const int* __restrict__ ei) {
    int e = blockIdx.x * blockDim.x + threadIdx.x;
    if (e >= EC) return;
    int h = ei[e], t = ei[EC + e];
    int p = atomicAdd(&g_cur[h], 1);
    g_idx[p] = e;
    int q = atomicAdd(&g_cur[NE + t], 1);
    g_idx[q] = e;
}

// ---- fma 8 halfs into fp32 accumulators ----
__device__ __forceinline__ void fma8(float* acc, uint4 p, float a) {
    __half2* h = reinterpret_cast<__half2*>(&p);
    #pragma unroll
    for (int q = 0; q < 4; q++) {
        float2 f = __half22float2(h[q]);
        acc[2 * q]     += a * f.x;
        acc[2 * q + 1] += a * f.y;
    }
}

// ---- segment softmax + weighted half-table accumulation ----
__device__ __forceinline__ void seg_accum(int base, int deg, int lane,
                                          const float* __restrict__ lg,
                                          const int* __restrict__ rel,
                                          const __half* __restrict__ table,
                                          float* acc) {
    if (deg <= 0) return;
    if (deg <= 32) {
        float l = -CUDART_INF_F;
        int r = 0;
        if (lane < deg) {
            int e = g_idx[base + lane];
            l = lg[e];
            r = rel[e];
        }
        float m = l;
        #pragma unroll
        for (int o = 16; o; o >>= 1) m = fmaxf(m, __shfl_xor_sync(0xFFFFFFFFu, m, o));
        float z = (lane < deg) ? __expf(l - m) : 0.0f;
        float s = z;
        #pragma unroll
        for (int o = 16; o; o >>= 1) s += __shfl_xor_sync(0xFFFFFFFFu, s, o);
        float a_own = z / (s + 1e-16f);
        for (int j = 0; j < deg; j++) {
            float a = __shfl_sync(0xFFFFFFFFu, a_own, j);
            int rj  = __shfl_sync(0xFFFFFFFFu, r, j);
            uint4 p = ((const uint4*)(table + (size_t)rj * OUTD))[lane];
            fma8(acc, p, a);
        }
    } else {
        float m = -CUDART_INF_F;
        for (int j = lane; j < deg; j += 32) m = fmaxf(m, lg[g_idx[base + j]]);
        #pragma unroll
        for (int o = 16; o; o >>= 1) m = fmaxf(m, __shfl_xor_sync(0xFFFFFFFFu, m, o));
        float s = 0.0f;
        for (int j = lane; j < deg; j += 32) s += __expf(lg[g_idx[base + j]] - m);
        #pragma unroll
        for (int o = 16; o; o >>= 1) s += __shfl_xor_sync(0xFFFFFFFFu, s, o);
        float inv = 1.0f / (s + 1e-16f);
        for (int c0 = 0; c0 < deg; c0 += 32) {
            int j = c0 + lane;
            float a_own = 0.0f;
            int r = 0;
            if (j < deg) {
                int e = g_idx[base + j];
                a_own = __expf(lg[e] - m) * inv;
                r = rel[e];
            }
            int cnt = min(32, deg - c0);
            for (int jj = 0; jj < cnt; jj++) {
                float a = __shfl_sync(0xFFFFFFFFu, a_own, jj);
                int rj  = __shfl_sync(0xFFFFFFFFu, r, jj);
                uint4 p = ((const uint4*)(table + (size_t)rj * OUTD))[lane];
                fma8(acc, p, a);
            }
        }
    }
}

// ---- gather: one warp per node, both directions, single row store ----
__global__ void k_gather(const int* __restrict__ rel,
                         const float* __restrict__ br,
                         float* __restrict__ out) {
    int n = (blockIdx.x * blockDim.x + threadIdx.x) >> 5;
    int lane = threadIdx.x & 31;
    if (n >= NE) return;

    float acc[8];
    #pragma unroll
    for (int q = 0; q < 8; q++) acc[q] = 0.0f;

    seg_accum(g_off[n],      g_hist[n],      lane, g_lh, rel, g_tWh, acc);
    seg_accum(g_off[NE + n], g_hist[NE + n], lane, g_lt, rel, g_tWt, acc);

    float4 b0 = ((const float4*)(br + lane * 8))[0];
    float4 b1 = ((const float4*)(br + lane * 8))[1];
    float4* o = (float4*)(out + (size_t)n * OUTD + lane * 8);
    o[0] = make_float4(acc[0] + b0.x, acc[1] + b0.y, acc[2] + b0.z, acc[3] + b0.w);
    o[1] = make_float4(acc[4] + b1.x, acc[5] + b1.y, acc[6] + b1.z, acc[7] + b1.w);
}

extern "C" void kernel_launch(void* const* d_in, const int* in_sizes, int n_in,
                              void* d_out, int out_size) {
    const float* x_e  = (const float*)d_in[0];
    const float* x_r  = (const float*)d_in[1];
    const int*   ei   = (const int*)d_in[2];
    const int*   rel  = (const int*)d_in[3];
    const float* w_ah = (const float*)d_in[5];
    const float* w_at = (const float*)d_in[6];
    const float* w_ar = (const float*)d_in[7];
    const float* W1   = (const float*)d_in[8];
    const float* b1   = (const float*)d_in[9];
    const float* W2   = (const float*)d_in[10];
    const float* b2   = (const float*)d_in[11];
    const float* Wr   = (const float*)d_in[12];
    const float* br   = (const float*)d_in[13];
    float* out = (float*)d_out;

    k_front<<<FRONT_NB, 1024>>>(x_r, W1, b1, W2, b2, Wr, x_e, w_ah, w_at, w_ar);
    k_logits<<<(EC + 255) / 256, 256>>>(ei, rel);
    k_scan1<<<SCAN_NB, SCAN_B>>>();
    k_scan2<<<1, 32>>>();
    k_scan3<<<(N2 + 255) / 256, 256>>>();
    k_fill<<<(EC + 255) / 256, 256>>>(ei);
    k_gather<<<(NE + 7) / 8, 256>>>(rel, br, out);
}

// round 12
// speedup vs baseline: 1.2482x; 1.0306x over previous
#include <cuda_runtime.h>
#include <cuda_fp16.h>
#include <math_constants.h>

#define NE 100000
#define NR 1000
#define EC 1000000
#define HID 128
#define OUTD 256
#define N2 (2 * NE)
#define SCAN_B 1024
#define SCAN_NB ((N2 + SCAN_B - 1) / SCAN_B)   // 196
#define RT 8                                    // relations per MLP block

// block-range dispatch for the fused front kernel
#define MLP_NB 125
#define Z_NB   ((N2 + 1023) / 1024)            // 196
#define NS_NB  ((NE + 31) / 32)                // 3125  (warp per node, 32 warps/block)
#define RS_NB  ((NR + 31) / 32)                // 32
#define FRONT_NB (MLP_NB + Z_NB + NS_NB + RS_NB)

// ---- scratch (device globals: allocation-free) ----
__device__ float  g_eh[NE];
__device__ float  g_et[NE];
__device__ float  g_er[NR];
__device__ float  g_lh[EC];
__device__ float  g_lt[EC];
__device__ __half g_tWh[NR * OUTD];
__device__ __half g_tWt[NR * OUTD];
__device__ int    g_hist[N2];
__device__ int    g_off[N2];
__device__ int    g_cur[N2];
__device__ int    g_idx[2 * EC];
__device__ int    g_part[SCAN_NB];
__device__ int    g_partoff[SCAN_NB];

// ---- fused front kernel: MLP blocks + zero_hist + node_scores + rel_scores ----
__global__ __launch_bounds__(1024) void k_front(
        const float* __restrict__ xr,
        const float* __restrict__ W1, const float* __restrict__ b1,
        const float* __restrict__ W2, const float* __restrict__ b2,
        const float* __restrict__ Wr,
        const float* __restrict__ xe,
        const float* __restrict__ wah, const float* __restrict__ wat,
        const float* __restrict__ war) {
    __shared__ float xs[RT][HID];        // x_r rows; becomes msg after layer 2
    __shared__ float hs[RT][2 * HID];    // hidden layer
    __shared__ float red[8192];          // 32 KB reduction buffer
    int bid = blockIdx.x;
    int tid = threadIdx.x;               // 1024 threads

    if (bid < MLP_NB) {
        // ================= fused relation MLP + W_r fold =================
        int r0 = bid * RT;
        int rh = tid >> 8;               // relation subset: rels rh*2, rh*2+1

        for (int i = tid; i < RT * HID; i += 1024) {
            int rr = i >> 7, c = i & 127;
            xs[rr][c] = xr[(size_t)(r0 + rr) * HID + c];
        }
        __syncthreads();

        // layer 1: hs[i][c] = b1[c] + sum_k xs[i][k] * W1[k*256+c]
        {
            int kk = (tid >> 6) & 3;     // k-group 0..3
            int u  = tid & 63;           // cols 4u..4u+3
            float4 acc[2];
            #pragma unroll
            for (int i = 0; i < 2; i++) acc[i] = make_float4(0.f, 0.f, 0.f, 0.f);
            #pragma unroll 4
            for (int m = 0; m < 32; m++) {
                int k = kk + 4 * m;
                float4 w = *(const float4*)&W1[k * 256 + 4 * u];
                #pragma unroll
                for (int i = 0; i < 2; i++) {
                    float x = xs[rh * 2 + i][k];
                    acc[i].x += x * w.x; acc[i].y += x * w.y;
                    acc[i].z += x * w.z; acc[i].w += x * w.w;
                }
            }
            #pragma unroll
            for (int i = 0; i < 2; i++)
                *(float4*)&red[(kk * 8 + rh * 2 + i) * 256 + 4 * u] = acc[i];
            __syncthreads();
            #pragma unroll
            for (int p = 0; p < 2; p++) {
                int idx = p * 1024 + tid;      // 2048 outputs
                int i = idx >> 8, c = idx & 255;
                hs[i][c] = b1[c] + red[(0 + i) * 256 + c] + red[(8 + i) * 256 + c]
                         + red[(16 + i) * 256 + c] + red[(24 + i) * 256 + c];
            }
            __syncthreads();
        }

        // layer 2 + residual
        {
            int jj = (tid >> 5) & 7;     // j-group 0..7
            int u  = tid & 31;           // cols 4u..4u+3
            float4 acc[2];
            #pragma unroll
            for (int i = 0; i < 2; i++) acc[i] = make_float4(0.f, 0.f, 0.f, 0.f);
            #pragma unroll 4
            for (int m = 0; m < 32; m++) {
                int j = jj + 8 * m;
                float4 w = *(const float4*)&W2[j * 128 + 4 * u];
                #pragma unroll
                for (int i = 0; i < 2; i++) {
                    float x = hs[rh * 2 + i][j];
                    acc[i].x += x * w.x; acc[i].y += x * w.y;
                    acc[i].z += x * w.z; acc[i].w += x * w.w;
                }
            }
            #pragma unroll
            for (int i = 0; i < 2; i++)
                *(float4*)&red[(jj * 8 + rh * 2 + i) * 128 + 4 * u] = acc[i];
            __syncthreads();
            {
                int idx = tid;                 // 1024 outputs
                int i = idx >> 7, c = idx & 127;
                float v = b2[c];
                #pragma unroll
                for (int g = 0; g < 8; g++) v += red[(g * 8 + i) * 128 + c];
                xs[i][c] += v;                 // msg = x_r + mlp(x_r)
            }
            __syncthreads();
        }

        // layer 3: folded tables
        {
            int half = (tid >> 7) & 1;   // 0: h-table, 1: t-table
            int kk   = (tid >> 6) & 1;   // k-group 0,1
            int u    = tid & 63;         // cols 4u..4u+3
            float4 acc[2];
            #pragma unroll
            for (int i = 0; i < 2; i++) acc[i] = make_float4(0.f, 0.f, 0.f, 0.f);
            #pragma unroll 4
            for (int m = 0; m < 64; m++) {
                int k = kk + 2 * m;
                float4 w = *(const float4*)&Wr[(half * 128 + k) * 256 + 4 * u];
                #pragma unroll
                for (int i = 0; i < 2; i++) {
                    float x = xs[rh * 2 + i][k];
                    acc[i].x += x * w.x; acc[i].y += x * w.y;
                    acc[i].z += x * w.z; acc[i].w += x * w.w;
                }
            }
            #pragma unroll
            for (int i = 0; i < 2; i++)
                *(float4*)&red[((kk * 2 + half) * 8 + rh * 2 + i) * 256 + 4 * u] = acc[i];
            __syncthreads();
            #pragma unroll
            for (int p = 0; p < 4; p++) {
                int idx = p * 1024 + tid;      // 4096 outputs
                int c = idx & 255;
                int q = idx >> 8;              // 0..15
                int i = q & 7, hf = q >> 3;
                float v = red[((0 + hf) * 8 + i) * 256 + c]
                        + red[((2 + hf) * 8 + i) * 256 + c];
                if (hf == 0) g_tWh[(size_t)(r0 + i) * OUTD + c] = __float2half(v);
                else         g_tWt[(size_t)(r0 + i) * OUTD + c] = __float2half(v);
            }
        }
    } else if (bid < MLP_NB + Z_NB) {
        // ================= zero histograms =================
        int i = (bid - MLP_NB) * 1024 + tid;
        if (i < N2) g_hist[i] = 0;
    } else if (bid < MLP_NB + Z_NB + NS_NB) {
        // ================= per-entity attention scores (warp per node) =====
        int warp = (bid - MLP_NB - Z_NB) * 32 + (tid >> 5);
        int lane = tid & 31;
        if (warp < NE) {
            const float4* row = (const float4*)(xe + (size_t)warp * HID);
            float4 v = row[lane];
            float4 a = ((const float4*)wah)[lane];
            float4 b = ((const float4*)wat)[lane];
            float sh = v.x * a.x + v.y * a.y + v.z * a.z + v.w * a.w;
            float st = v.x * b.x + v.y * b.y + v.z * b.z + v.w * b.w;
            #pragma unroll
            for (int o = 16; o; o >>= 1) {
                sh += __shfl_xor_sync(0xFFFFFFFFu, sh, o);
                st += __shfl_xor_sync(0xFFFFFFFFu, st, o);
            }
            if (lane == 0) { g_eh[warp] = sh; g_et[warp] = st; }
        }
    } else {
        // ================= per-relation attention scores (warp per rel) ====
        int warp = (bid - MLP_NB - Z_NB - NS_NB) * 32 + (tid >> 5);
        int lane = tid & 31;
        if (warp < NR) {
            const float4* row = (const float4*)(xr + (size_t)warp * HID);
            float4 v = row[lane];
            float4 a = ((const float4*)war)[lane];
            float s = v.x * a.x + v.y * a.y + v.z * a.z + v.w * a.w;
            #pragma unroll
            for (int o = 16; o; o >>= 1) s += __shfl_xor_sync(0xFFFFFFFFu, s, o);
            if (lane == 0) g_er[warp] = s;
        }
    }
}

// ---- edge pass: logits + degree histogram ----
__global__ void k_logits(const int* __restrict__ ei, const int* __restrict__ rel) {
    int e = blockIdx.x * blockDim.x + threadIdx.x;
    if (e >= EC) return;
    int h = ei[e], t = ei[EC + e], r = rel[e];
    float er = g_er[r];
    float lh = g_eh[h] + er;
    lh = lh > 0.0f ? lh : 0.01f * lh;
    float lt = g_et[t] + er;
    lt = lt > 0.0f ? lt : 0.01f * lt;
    g_lh[e] = lh;
    g_lt[e] = lt;
    atomicAdd(&g_hist[h], 1);
    atomicAdd(&g_hist[NE + t], 1);
}

// ---- scan stage 1 ----
__global__ void k_scan1() {
    __shared__ int sh[SCAN_B];
    int t = threadIdx.x;
    int i = blockIdx.x * SCAN_B + t;
    int v = (i < N2) ? g_hist[i] : 0;
    sh[t] = v;
    __syncthreads();
    #pragma unroll
    for (int d = 1; d < SCAN_B; d <<= 1) {
        int x = (t >= d) ? sh[t - d] : 0;
        __syncthreads();
        sh[t] += x;
        __syncthreads();
    }
    if (i < N2) g_off[i] = sh[t] - v;
    if (t == SCAN_B - 1) g_part[blockIdx.x] = sh[t];
}

// ---- scan stage 2: parallel block scan of the 196 partials ----
__global__ void k_scan2() {
    __shared__ int sh[256];
    int t = threadIdx.x;
    int v = (t < SCAN_NB) ? g_part[t] : 0;
    sh[t] = v;
    __syncthreads();
    #pragma unroll
    for (int d = 1; d < 256; d <<= 1) {
        int x = (t >= d) ? sh[t - d] : 0;
        __syncthreads();
        sh[t] += x;
        __syncthreads();
    }
    if (t < SCAN_NB) g_partoff[t] = sh[t] - v;   // exclusive
}

// ---- scan stage 3 ----
__global__ void k_scan3() {
    int i = blockIdx.x * blockDim.x + threadIdx.x;
    if (i < N2) {
        int o = g_off[i] + g_partoff[i / SCAN_B];
        g_off[i] = o;
        g_cur[i] = o;
    }
}

// ---- CSR fill ----
__global__ void k_fill(const int* __restrict__ ei) {
    int e = blockIdx.x * blockDim.x + threadIdx.x;
    if (e >= EC) return;
    int h = ei[e], t = ei[EC + e];
    int p = atomicAdd(&g_cur[h], 1);
    g_idx[p] = e;
    int q = atomicAdd(&g_cur[NE + t], 1);
    g_idx[q] = e;
}

// ---- fma 8 halfs into fp32 accumulators ----
__device__ __forceinline__ void fma8(float* acc, uint4 p, float a) {
    __half2* h = reinterpret_cast<__half2*>(&p);
    #pragma unroll
    for (int q = 0; q < 4; q++) {
        float2 f = __half22float2(h[q]);
        acc[2 * q]     += a * f.x;
        acc[2 * q + 1] += a * f.y;
    }
}

// ---- segment softmax + weighted half-table accumulation ----
__device__ __forceinline__ void seg_accum(int base, int deg, int lane,
                                          const float* __restrict__ lg,
                                          const int* __restrict__ rel,
                                          const __half* __restrict__ table,
                                          float* acc) {
    if (deg <= 0) return;
    if (deg <= 32) {
        float l = -CUDART_INF_F;
        int r = 0;
        if (lane < deg) {
            int e = g_idx[base + lane];
            l = lg[e];
            r = rel[e];
        }
        float m = l;
        #pragma unroll
        for (int o = 16; o; o >>= 1) m = fmaxf(m, __shfl_xor_sync(0xFFFFFFFFu, m, o));
        float z = (lane < deg) ? __expf(l - m) : 0.0f;
        float s = z;
        #pragma unroll
        for (int o = 16; o; o >>= 1) s += __shfl_xor_sync(0xFFFFFFFFu, s, o);
        float a_own = z / (s + 1e-16f);
        for (int j = 0; j < deg; j++) {
            float a = __shfl_sync(0xFFFFFFFFu, a_own, j);
            int rj  = __shfl_sync(0xFFFFFFFFu, r, j);
            uint4 p = ((const uint4*)(table + (size_t)rj * OUTD))[lane];
            fma8(acc, p, a);
        }
    } else {
        float m = -CUDART_INF_F;
        for (int j = lane; j < deg; j += 32) m = fmaxf(m, lg[g_idx[base + j]]);
        #pragma unroll
        for (int o = 16; o; o >>= 1) m = fmaxf(m, __shfl_xor_sync(0xFFFFFFFFu, m, o));
        float s = 0.0f;
        for (int j = lane; j < deg; j += 32) s += __expf(lg[g_idx[base + j]] - m);
        #pragma unroll
        for (int o = 16; o; o >>= 1) s += __shfl_xor_sync(0xFFFFFFFFu, s, o);
        float inv = 1.0f / (s + 1e-16f);
        for (int c0 = 0; c0 < deg; c0 += 32) {
            int j = c0 + lane;
            float a_own = 0.0f;
            int r = 0;
            if (j < deg) {
                int e = g_idx[base + j];
                a_own = __expf(lg[e] - m) * inv;
                r = rel[e];
            }
            int cnt = min(32, deg - c0);
            for (int jj = 0; jj < cnt; jj++) {
                float a = __shfl_sync(0xFFFFFFFFu, a_own, jj);
                int rj  = __shfl_sync(0xFFFFFFFFu, r, jj);
                uint4 p = ((const uint4*)(table + (size_t)rj * OUTD))[lane];
                fma8(acc, p, a);
            }
        }
    }
}

// ---- gather: one warp per node, both directions, single row store ----
__global__ void k_gather(const int* __restrict__ rel,
                         const float* __restrict__ br,
                         float* __restrict__ out) {
    int n = (blockIdx.x * blockDim.x + threadIdx.x) >> 5;
    int lane = threadIdx.x & 31;
    if (n >= NE) return;

    float acc[8];
    #pragma unroll
    for (int q = 0; q < 8; q++) acc[q] = 0.0f;

    seg_accum(g_off[n],      g_hist[n],      lane, g_lh, rel, g_tWh, acc);
    seg_accum(g_off[NE + n], g_hist[NE + n], lane, g_lt, rel, g_tWt, acc);

    float4 b0 = ((const float4*)(br + lane * 8))[0];
    float4 b1 = ((const float4*)(br + lane * 8))[1];
    float4* o = (float4*)(out + (size_t)n * OUTD + lane * 8);
    o[0] = make_float4(acc[0] + b0.x, acc[1] + b0.y, acc[2] + b0.z, acc[3] + b0.w);
    o[1] = make_float4(acc[4] + b1.x, acc[5] + b1.y, acc[6] + b1.z, acc[7] + b1.w);
}

extern "C" void kernel_launch(void* const* d_in, const int* in_sizes, int n_in,
                              void* d_out, int out_size) {
    const float* x_e  = (const float*)d_in[0];
    const float* x_r  = (const float*)d_in[1];
    const int*   ei   = (const int*)d_in[2];
    const int*   rel  = (const int*)d_in[3];
    const float* w_ah = (const float*)d_in[5];
    const float* w_at = (const float*)d_in[6];
    const float* w_ar = (const float*)d_in[7];
    const float* W1   = (const float*)d_in[8];
    const float* b1   = (const float*)d_in[9];
    const float* W2   = (const float*)d_in[10];
    const float* b2   = (const float*)d_in[11];
    const float* Wr   = (const float*)d_in[12];
    const float* br   = (const float*)d_in[13];
    float* out = (float*)d_out;

    k_front<<<FRONT_NB, 1024>>>(x_r, W1, b1, W2, b2, Wr, x_e, w_ah, w_at, w_ar);
    k_logits<<<(EC + 255) / 256, 256>>>(ei, rel);
    k_scan1<<<SCAN_NB, SCAN_B>>>();
    k_scan2<<<1, 256>>>();
    k_scan3<<<(N2 + 255) / 256, 256>>>();
    k_fill<<<(EC + 255) / 256, 256>>>(ei);
    k_gather<<<(NE + 7) / 8, 256>>>(rel, br, out);
}

// round 13
// speedup vs baseline: 1.4082x; 1.1282x over previous
#include <cuda_runtime.h>
#include <cuda_fp16.h>
#include <math_constants.h>

#define NE 100000
#define NR 1000
#define EC 1000000
#define HID 128
#define OUTD 256
#define N2 (2 * NE)
#define SCAN_B 1024
#define SCAN_NB ((N2 + SCAN_B - 1) / SCAN_B)   // 196
#define RT 8                                    // relations per MLP block

// block-range dispatch for the fused front kernel
#define MLP_NB 125
#define NS_NB  ((NE + 31) / 32)                // 3125  (warp per node, 32 warps/block)
#define RS_NB  ((NR + 31) / 32)                // 32
#define H_NB   ((EC + 1023) / 1024)            // 977   (histogram count blocks)
#define FRONT_NB (MLP_NB + NS_NB + RS_NB + H_NB)

// ---- scratch (device globals: allocation-free) ----
__device__ float  g_eh[NE];
__device__ float  g_et[NE];
__device__ float  g_er[NR];
__device__ __half g_tWh[NR * OUTD];
__device__ __half g_tWt[NR * OUTD];
__device__ int    g_hist[N2];
__device__ int    g_off[N2];
__device__ int    g_cur[N2];
__device__ float2 g_pk[2 * EC];        // per-slot packed (logit, rel-bits)
__device__ int    g_part[SCAN_NB];
__device__ int    g_partoff[SCAN_NB];

// ---- zero histograms (must precede front's hist-count blocks) ----
__global__ void k_zero() {
    int i = blockIdx.x * 1024 + threadIdx.x;
    if (i < N2) g_hist[i] = 0;
}

// ---- fused front kernel: MLP + node_scores + rel_scores + hist count ----
__global__ __launch_bounds__(1024) void k_front(
        const float* __restrict__ xr,
        const float* __restrict__ W1, const float* __restrict__ b1,
        const float* __restrict__ W2, const float* __restrict__ b2,
        const float* __restrict__ Wr,
        const float* __restrict__ xe,
        const float* __restrict__ wah, const float* __restrict__ wat,
        const float* __restrict__ war,
        const int* __restrict__ ei) {
    __shared__ float xs[RT][HID];        // x_r rows; becomes msg after layer 2
    __shared__ float hs[RT][2 * HID];    // hidden layer
    __shared__ float red[8192];          // 32 KB reduction buffer
    int bid = blockIdx.x;
    int tid = threadIdx.x;               // 1024 threads

    if (bid < MLP_NB) {
        // ================= fused relation MLP + W_r fold =================
        int r0 = bid * RT;
        int rh = tid >> 8;               // relation subset: rels rh*2, rh*2+1

        for (int i = tid; i < RT * HID; i += 1024) {
            int rr = i >> 7, c = i & 127;
            xs[rr][c] = xr[(size_t)(r0 + rr) * HID + c];
        }
        __syncthreads();

        // layer 1: hs[i][c] = b1[c] + sum_k xs[i][k] * W1[k*256+c]
        {
            int kk = (tid >> 6) & 3;     // k-group 0..3
            int u  = tid & 63;           // cols 4u..4u+3
            float4 acc[2];
            #pragma unroll
            for (int i = 0; i < 2; i++) acc[i] = make_float4(0.f, 0.f, 0.f, 0.f);
            #pragma unroll 4
            for (int m = 0; m < 32; m++) {
                int k = kk + 4 * m;
                float4 w = *(const float4*)&W1[k * 256 + 4 * u];
                #pragma unroll
                for (int i = 0; i < 2; i++) {
                    float x = xs[rh * 2 + i][k];
                    acc[i].x += x * w.x; acc[i].y += x * w.y;
                    acc[i].z += x * w.z; acc[i].w += x * w.w;
                }
            }
            #pragma unroll
            for (int i = 0; i < 2; i++)
                *(float4*)&red[(kk * 8 + rh * 2 + i) * 256 + 4 * u] = acc[i];
            __syncthreads();
            #pragma unroll
            for (int p = 0; p < 2; p++) {
                int idx = p * 1024 + tid;      // 2048 outputs
                int i = idx >> 8, c = idx & 255;
                hs[i][c] = b1[c] + red[(0 + i) * 256 + c] + red[(8 + i) * 256 + c]
                         + red[(16 + i) * 256 + c] + red[(24 + i) * 256 + c];
            }
            __syncthreads();
        }

        // layer 2 + residual
        {
            int jj = (tid >> 5) & 7;     // j-group 0..7
            int u  = tid & 31;           // cols 4u..4u+3
            float4 acc[2];
            #pragma unroll
            for (int i = 0; i < 2; i++) acc[i] = make_float4(0.f, 0.f, 0.f, 0.f);
            #pragma unroll 4
            for (int m = 0; m < 32; m++) {
                int j = jj + 8 * m;
                float4 w = *(const float4*)&W2[j * 128 + 4 * u];
                #pragma unroll
                for (int i = 0; i < 2; i++) {
                    float x = hs[rh * 2 + i][j];
                    acc[i].x += x * w.x; acc[i].y += x * w.y;
                    acc[i].z += x * w.z; acc[i].w += x * w.w;
                }
            }
            #pragma unroll
            for (int i = 0; i < 2; i++)
                *(float4*)&red[(jj * 8 + rh * 2 + i) * 128 + 4 * u] = acc[i];
            __syncthreads();
            {
                int idx = tid;                 // 1024 outputs
                int i = idx >> 7, c = idx & 127;
                float v = b2[c];
                #pragma unroll
                for (int g = 0; g < 8; g++) v += red[(g * 8 + i) * 128 + c];
                xs[i][c] += v;                 // msg = x_r + mlp(x_r)
            }
            __syncthreads();
        }

        // layer 3: folded tables
        {
            int half = (tid >> 7) & 1;   // 0: h-table, 1: t-table
            int kk   = (tid >> 6) & 1;   // k-group 0,1
            int u    = tid & 63;         // cols 4u..4u+3
            float4 acc[2];
            #pragma unroll
            for (int i = 0; i < 2; i++) acc[i] = make_float4(0.f, 0.f, 0.f, 0.f);
            #pragma unroll 4
            for (int m = 0; m < 64; m++) {
                int k = kk + 2 * m;
                float4 w = *(const float4*)&Wr[(half * 128 + k) * 256 + 4 * u];
                #pragma unroll
                for (int i = 0; i < 2; i++) {
                    float x = xs[rh * 2 + i][k];
                    acc[i].x += x * w.x; acc[i].y += x * w.y;
                    acc[i].z += x * w.z; acc[i].w += x * w.w;
                }
            }
            #pragma unroll
            for (int i = 0; i < 2; i++)
                *(float4*)&red[((kk * 2 + half) * 8 + rh * 2 + i) * 256 + 4 * u] = acc[i];
            __syncthreads();
            #pragma unroll
            for (int p = 0; p < 4; p++) {
                int idx = p * 1024 + tid;      // 4096 outputs
                int c = idx & 255;
                int q = idx >> 8;              // 0..15
                int i = q & 7, hf = q >> 3;
                float v = red[((0 + hf) * 8 + i) * 256 + c]
                        + red[((2 + hf) * 8 + i) * 256 + c];
                if (hf == 0) g_tWh[(size_t)(r0 + i) * OUTD + c] = __float2half(v);
                else         g_tWt[(size_t)(r0 + i) * OUTD + c] = __float2half(v);
            }
        }
    } else if (bid < MLP_NB + NS_NB) {
        // ================= per-entity attention scores (warp per node) =====
        int warp = (bid - MLP_NB) * 32 + (tid >> 5);
        int lane = tid & 31;
        if (warp < NE) {
            const float4* row = (const float4*)(xe + (size_t)warp * HID);
            float4 v = row[lane];
            float4 a = ((const float4*)wah)[lane];
            float4 b = ((const float4*)wat)[lane];
            float sh = v.x * a.x + v.y * a.y + v.z * a.z + v.w * a.w;
            float st = v.x * b.x + v.y * b.y + v.z * b.z + v.w * b.w;
            #pragma unroll
            for (int o = 16; o; o >>= 1) {
                sh += __shfl_xor_sync(0xFFFFFFFFu, sh, o);
                st += __shfl_xor_sync(0xFFFFFFFFu, st, o);
            }
            if (lane == 0) { g_eh[warp] = sh; g_et[warp] = st; }
        }
    } else if (bid < MLP_NB + NS_NB + RS_NB) {
        // ================= per-relation attention scores (warp per rel) ====
        int warp = (bid - MLP_NB - NS_NB) * 32 + (tid >> 5);
        int lane = tid & 31;
        if (warp < NR) {
            const float4* row = (const float4*)(xr + (size_t)warp * HID);
            float4 v = row[lane];
            float4 a = ((const float4*)war)[lane];
            float s = v.x * a.x + v.y * a.y + v.z * a.z + v.w * a.w;
            #pragma unroll
            for (int o = 16; o; o >>= 1) s += __shfl_xor_sync(0xFFFFFFFFu, s, o);
            if (lane == 0) g_er[warp] = s;
        }
    } else {
        // ================= degree histogram (needs only ei) ================
        int e = (bid - MLP_NB - NS_NB - RS_NB) * 1024 + tid;
        if (e < EC) {
            atomicAdd(&g_hist[ei[e]], 1);
            atomicAdd(&g_hist[NE + ei[EC + e]], 1);
        }
    }
}

// ---- scan stage 1 ----
__global__ void k_scan1() {
    __shared__ int sh[SCAN_B];
    int t = threadIdx.x;
    int i = blockIdx.x * SCAN_B + t;
    int v = (i < N2) ? g_hist[i] : 0;
    sh[t] = v;
    __syncthreads();
    #pragma unroll
    for (int d = 1; d < SCAN_B; d <<= 1) {
        int x = (t >= d) ? sh[t - d] : 0;
        __syncthreads();
        sh[t] += x;
        __syncthreads();
    }
    if (i < N2) g_off[i] = sh[t] - v;
    if (t == SCAN_B - 1) g_part[blockIdx.x] = sh[t];
}

// ---- scan stage 2: parallel block scan of the 196 partials ----
__global__ void k_scan2() {
    __shared__ int sh[256];
    int t = threadIdx.x;
    int v = (t < SCAN_NB) ? g_part[t] : 0;
    sh[t] = v;
    __syncthreads();
    #pragma unroll
    for (int d = 1; d < 256; d <<= 1) {
        int x = (t >= d) ? sh[t - d] : 0;
        __syncthreads();
        sh[t] += x;
        __syncthreads();
    }
    if (t < SCAN_NB) g_partoff[t] = sh[t] - v;   // exclusive
}

// ---- scan stage 3 ----
__global__ void k_scan3() {
    int i = blockIdx.x * blockDim.x + threadIdx.x;
    if (i < N2) {
        int o = g_off[i] + g_partoff[i / SCAN_B];
        g_off[i] = o;
        g_cur[i] = o;
    }
}

// ---- fused CSR fill + logits: writes packed (logit, rel) per slot ----
__global__ void k_fill(const int* __restrict__ ei, const int* __restrict__ rel) {
    int e = blockIdx.x * blockDim.x + threadIdx.x;
    if (e >= EC) return;
    int h = ei[e], t = ei[EC + e], r = rel[e];
    float er = g_er[r];
    float rbits = __int_as_float(r);
    float lh = g_eh[h] + er;
    lh = lh > 0.0f ? lh : 0.01f * lh;
    float lt = g_et[t] + er;
    lt = lt > 0.0f ? lt : 0.01f * lt;
    int p = atomicAdd(&g_cur[h], 1);
    g_pk[p] = make_float2(lh, rbits);
    int q = atomicAdd(&g_cur[NE + t], 1);
    g_pk[q] = make_float2(lt, rbits);
}

// ---- fma 8 halfs into fp32 accumulators ----
__device__ __forceinline__ void fma8(float* acc, uint4 p, float a) {
    __half2* h = reinterpret_cast<__half2*>(&p);
    #pragma unroll
    for (int q = 0; q < 4; q++) {
        float2 f = __half22float2(h[q]);
        acc[2 * q]     += a * f.x;
        acc[2 * q + 1] += a * f.y;
    }
}

// ---- segment softmax + weighted half-table accumulation (packed slots) ----
__device__ __forceinline__ void seg_accum(int base, int deg, int lane,
                                          const __half* __restrict__ table,
                                          float* acc) {
    if (deg <= 0) return;
    if (deg <= 32) {
        float l = -CUDART_INF_F;
        int r = 0;
        if (lane < deg) {
            float2 pk = g_pk[base + lane];     // one coalesced 8B load
            l = pk.x;
            r = __float_as_int(pk.y);
        }
        float m = l;
        #pragma unroll
        for (int o = 16; o; o >>= 1) m = fmaxf(m, __shfl_xor_sync(0xFFFFFFFFu, m, o));
        float z = (lane < deg) ? __expf(l - m) : 0.0f;
        float s = z;
        #pragma unroll
        for (int o = 16; o; o >>= 1) s += __shfl_xor_sync(0xFFFFFFFFu, s, o);
        float a_own = z / (s + 1e-16f);
        for (int j = 0; j < deg; j++) {
            float a = __shfl_sync(0xFFFFFFFFu, a_own, j);
            int rj  = __shfl_sync(0xFFFFFFFFu, r, j);
            uint4 p = ((const uint4*)(table + (size_t)rj * OUTD))[lane];
            fma8(acc, p, a);
        }
    } else {
        float m = -CUDART_INF_F;
        for (int j = lane; j < deg; j += 32) m = fmaxf(m, g_pk[base + j].x);
        #pragma unroll
        for (int o = 16; o; o >>= 1) m = fmaxf(m, __shfl_xor_sync(0xFFFFFFFFu, m, o));
        float s = 0.0f;
        for (int j = lane; j < deg; j += 32) s += __expf(g_pk[base + j].x - m);
        #pragma unroll
        for (int o = 16; o; o >>= 1) s += __shfl_xor_sync(0xFFFFFFFFu, s, o);
        float inv = 1.0f / (s + 1e-16f);
        for (int c0 = 0; c0 < deg; c0 += 32) {
            int j = c0 + lane;
            float a_own = 0.0f;
            int r = 0;
            if (j < deg) {
                float2 pk = g_pk[base + j];
                a_own = __expf(pk.x - m) * inv;
                r = __float_as_int(pk.y);
            }
            int cnt = min(32, deg - c0);
            for (int jj = 0; jj < cnt; jj++) {
                float a = __shfl_sync(0xFFFFFFFFu, a_own, jj);
                int rj  = __shfl_sync(0xFFFFFFFFu, r, jj);
                uint4 p = ((const uint4*)(table + (size_t)rj * OUTD))[lane];
                fma8(acc, p, a);
            }
        }
    }
}

// ---- gather: one warp per node, both directions, single row store ----
__global__ void k_gather(const float* __restrict__ br, float* __restrict__ out) {
    int n = (blockIdx.x * blockDim.x + threadIdx.x) >> 5;
    int lane = threadIdx.x & 31;
    if (n >= NE) return;

    float acc[8];
    #pragma unroll
    for (int q = 0; q < 8; q++) acc[q] = 0.0f;

    seg_accum(g_off[n],      g_hist[n],      lane, g_tWh, acc);
    seg_accum(g_off[NE + n], g_hist[NE + n], lane, g_tWt, acc);

    float4 b0 = ((const float4*)(br + lane * 8))[0];
    float4 b1 = ((const float4*)(br + lane * 8))[1];
    float4* o = (float4*)(out + (size_t)n * OUTD + lane * 8);
    o[0] = make_float4(acc[0] + b0.x, acc[1] + b0.y, acc[2] + b0.z, acc[3] + b0.w);
    o[1] = make_float4(acc[4] + b1.x, acc[5] + b1.y, acc[6] + b1.z, acc[7] + b1.w);
}

extern "C" void kernel_launch(void* const* d_in, const int* in_sizes, int n_in,
                              void* d_out, int out_size) {
    const float* x_e  = (const float*)d_in[0];
    const float* x_r  = (const float*)d_in[1];
    const int*   ei   = (const int*)d_in[2];
    const int*   rel  = (const int*)d_in[3];
    const float* w_ah = (const float*)d_in[5];
    const float* w_at = (const float*)d_in[6];
    const float* w_ar = (const float*)d_in[7];
    const float* W1   = (const float*)d_in[8];
    const float* b1   = (const float*)d_in[9];
    const float* W2   = (const float*)d_in[10];
    const float* b2   = (const float*)d_in[11];
    const float* Wr   = (const float*)d_in[12];
    const float* br   = (const float*)d_in[13];
    float* out = (float*)d_out;

    k_zero<<<(N2 + 1023) / 1024, 1024>>>();
    k_front<<<FRONT_NB, 1024>>>(x_r, W1, b1, W2, b2, Wr, x_e, w_ah, w_at, w_ar, ei);
    k_scan1<<<SCAN_NB, SCAN_B>>>();
    k_scan2<<<1, 256>>>();
    k_scan3<<<(N2 + 255) / 256, 256>>>();
    k_fill<<<(EC + 255) / 256, 256>>>(ei, rel);
    k_gather<<<(NE + 7) / 8, 256>>>(br, out);
}